// round 17
// baseline (speedup 1.0000x reference)
#include <cuda_runtime.h>

// Local cost volume (SpatialCorrelationSampler, kernel_size=1, patch 9x9):
// out[b, p, y, x] = sum_c t1[b,c,y,x] * t2[b,c,y+di,x+dj],  p=(di+4)*9+(dj+4)
// t1,t2 [4,128,128,256] f32 -> out [4,81,128,256] f32.
//
// Y-PAIR kernel: CTA = 160 threads = 5 warps, one x-tile (128 px), TWO
// output rows (y0, y0+1). Warp w owns t2 row r = y0-4 + dig*5 + w; that row
// feeds out(y0, di=r-y0+4) AND out(y0+1, di=r-y0+3) with shared window regs.
// R17: t1 is read by direct LDG (no staging; L2-shared across dig pair) --
// cuts cp.async fill ops 28% (fill-bound per R16 analysis) -- and the t2
// pipeline is 3-stage with wait_group 1 for two chunk-intervals of flight.

#define CH 128
#define HH 128
#define WW 256
#define MD 4
#define DD 9
#define CC 4
#define XT 128
#define T2C 136           // 34 granules of 4 floats
#define HW (HH*WW)
#define NW 5              // t2 rows (= warps) per CTA
#define YP 2              // output rows per CTA
#define NTHREADS 160
#define NCHUNK 32
#define STAGES 3

#define T2_STG (CC*NW*T2C)      // 2720 floats
#define SMEM_BYTES (STAGES*T2_STG*4)   // 32,640 B

typedef unsigned long long u64;

__device__ __forceinline__ u64 pk(float lo, float hi) {
    u64 r; asm("mov.b64 %0, {%1,%2};" : "=l"(r) : "f"(lo), "f"(hi)); return r;
}
__device__ __forceinline__ void fma2(u64 &d, u64 a, u64 b) {
    asm("fma.rn.f32x2 %0, %1, %2, %0;" : "+l"(d) : "l"(a), "l"(b));
}
__device__ __forceinline__ float2 upk(u64 v) {
    float lo, hi; asm("mov.b64 {%0,%1}, %2;" : "=f"(lo), "=f"(hi) : "l"(v));
    return make_float2(lo, hi);
}
__device__ __forceinline__ void cpasync16(unsigned smem_addr, const void* gptr) {
    asm volatile("cp.async.cg.shared.global [%0], [%1], 16;" ::
                 "r"(smem_addr), "l"(gptr));
}

__global__ __launch_bounds__(NTHREADS, 3)
void corr_volume_kernel(const float* __restrict__ t1,
                        const float* __restrict__ t2,
                        float* __restrict__ out)
{
    extern __shared__ float sm[];
    float* s_t2 = sm;                       // [STAGES][CC][NW][T2C]

    const int tid   = threadIdx.x;
    const int wid   = tid >> 5;             // 0..4
    const int lane  = tid & 31;

    // bid = (((batch*64 + yp)*2 + xt)*2 + dig)   -- dig fastest
    const int blk   = blockIdx.x;           // 0..1023
    const int dig   = blk & 1;
    const int xt    = (blk >> 1) & 1;
    const int yp    = (blk >> 2) & 63;
    const int batch = blk >> 8;
    const int y0    = yp * YP;
    const int x0    = xt * XT;

    const int r_off = dig * NW + wid;       // 0..9
    const int gy    = y0 - MD + r_off;      // this warp's t2 row
    const bool vrow = (unsigned)gy < (unsigned)HH;     // warp-uniform
    const bool has_a = (r_off <= 8);        // out(y0,   di = r_off)
    const bool has_b = (r_off >= 1);        // out(y0+1, di = r_off-1)

    // halo: smem col j holds gx = x0 + j - 4; valid granules [lo, lo+33),
    // one pad granule per row at hpad.
    const int lo   = (xt == 0) ? 1 : 0;
    const int hpad = (xt == 0) ? 0 : 33;

    // ---- one-time zero of constant pad regions (all stages) ----
    {
        const float4 z = make_float4(0.f, 0.f, 0.f, 0.f);
        #pragma unroll
        for (int st = 0; st < STAGES; st++)
            #pragma unroll
            for (int cc = 0; cc < CC; cc++) {
                float* row = s_t2 + (size_t)st * T2_STG + (cc * NW + wid) * T2C;
                if (vrow) {
                    if (lane == 0) *(float4*)&row[4 * hpad] = z;
                } else {
                    *(float4*)&row[4 * lane] = z;
                    if (lane < 2) *(float4*)&row[4 * (32 + lane)] = z;
                }
            }
    }

    u64 accA[DD][2], accB[DD][2];
    #pragma unroll
    for (int d = 0; d < DD; d++) {
        accA[d][0] = 0ull; accA[d][1] = 0ull;
        accB[d][0] = 0ull; accB[d][1] = 0ull;
    }

    const int xl = lane * 4;

    // ---- t2 fill (per warp, own row): lane -> granule lo+lane, lane0 extra ----
    const unsigned t2b = (unsigned)__cvta_generic_to_shared(s_t2);
    const unsigned t2d1 = t2b + (unsigned)(wid * T2C + 4 * (lo + lane)) * 4;
    const unsigned t2d2 = t2b + (unsigned)(wid * T2C + 4 * (lo + 32)) * 4;
    const float* t2src = t2 + (size_t)batch * CH * HW
                            + (size_t)(vrow ? gy : 0) * WW + (x0 - 4 + 4 * lo);

    // ---- t1 direct-LDG base (row y0 / y0+1 for this lane's 4 px) ----
    const float* abase = t1 + (size_t)batch * CH * HW + (size_t)y0 * WW + x0 + xl;

    auto issue = [&](int chunk) {
        const int c0 = chunk * CC;
        const int st = chunk % STAGES;
        if (vrow) {
            const float* src = t2src + (size_t)c0 * HW;
            const unsigned so = (unsigned)(st * T2_STG) * 4;
            #pragma unroll
            for (int cc = 0; cc < CC; cc++) {
                const unsigned co = so + (unsigned)(cc * (NW * T2C)) * 4;
                cpasync16(t2d1 + co, src + (size_t)cc * HW + 4 * lane);
                if (lane == 0) cpasync16(t2d2 + co, src + (size_t)cc * HW + 128);
            }
        }
        asm volatile("cp.async.commit_group;");
    };

    issue(0);
    issue(1);

    for (int it = 0; it < NCHUNK; it++) {
        const int st = it % STAGES;
        if (it == NCHUNK - 1) asm volatile("cp.async.wait_group 0;");
        else                  asm volatile("cp.async.wait_group 1;");
        __syncthreads();               // chunk it visible; stage (it+2)%3 free
        if (it + 2 < NCHUNK) issue(it + 2);

        const float* b_t2 = s_t2 + (size_t)st * T2_STG;
        const float* ab = abase + (size_t)(it * CC) * HW;

        #pragma unroll
        for (int cc = 0; cc < CC; cc++) {
            float4 a0 = __ldg((const float4*)(ab + (size_t)cc * HW));
            float4 a1 = __ldg((const float4*)(ab + (size_t)cc * HW + WW));
            u64 A0 = pk(a0.x, a0.y), A1 = pk(a0.z, a0.w);
            u64 B0 = pk(a1.x, a1.y), B1 = pk(a1.z, a1.w);

            const float* tr = &b_t2[(cc * NW + wid) * T2C + xl];
            float4 v0 = *(const float4*)&tr[0];
            float4 v1 = *(const float4*)&tr[4];
            float4 v2 = *(const float4*)&tr[8];

            u64 P[6];
            P[0] = pk(v0.x, v0.y); P[1] = pk(v0.z, v0.w);
            P[2] = pk(v1.x, v1.y); P[3] = pk(v1.z, v1.w);
            P[4] = pk(v2.x, v2.y); P[5] = pk(v2.z, v2.w);
            u64 Q[5];
            Q[0] = pk(v0.y, v0.z); Q[1] = pk(v0.w, v1.x);
            Q[2] = pk(v1.y, v1.z); Q[3] = pk(v1.w, v2.x);
            Q[4] = pk(v2.y, v2.z);

            #pragma unroll
            for (int dj = 0; dj < DD; dj++) {
                const int h = dj >> 1;
                if ((dj & 1) == 0) {
                    fma2(accA[dj][0], A0, P[h + 0]);
                    fma2(accA[dj][1], A1, P[h + 1]);
                    fma2(accB[dj][0], B0, P[h + 0]);
                    fma2(accB[dj][1], B1, P[h + 1]);
                } else {
                    fma2(accA[dj][0], A0, Q[h + 0]);
                    fma2(accA[dj][1], A1, Q[h + 1]);
                    fma2(accB[dj][0], B0, Q[h + 0]);
                    fma2(accB[dj][1], B1, Q[h + 1]);
                }
            }
        }
    }

    // ---- write out ----
    if (has_a) {      // out(y0, di = r_off)
        size_t ob = (((size_t)batch * 81 + (size_t)r_off * DD) * HH + y0) * WW
                  + x0 + xl;
        #pragma unroll
        for (int dj = 0; dj < DD; dj++) {
            float2 p0 = upk(accA[dj][0]), p1 = upk(accA[dj][1]);
            *(float4*)&out[ob + (size_t)dj * HW] =
                make_float4(p0.x, p0.y, p1.x, p1.y);
        }
    }
    if (has_b) {      // out(y0+1, di = r_off-1)
        size_t ob = (((size_t)batch * 81 + (size_t)(r_off - 1) * DD) * HH
                  + (y0 + 1)) * WW + x0 + xl;
        #pragma unroll
        for (int dj = 0; dj < DD; dj++) {
            float2 p0 = upk(accB[dj][0]), p1 = upk(accB[dj][1]);
            *(float4*)&out[ob + (size_t)dj * HW] =
                make_float4(p0.x, p0.y, p1.x, p1.y);
        }
    }
}

extern "C" void kernel_launch(void* const* d_in, const int* in_sizes, int n_in,
                              void* d_out, int out_size)
{
    const float* t1 = (const float*)d_in[0];
    const float* t2 = (const float*)d_in[1];
    float* out = (float*)d_out;
    cudaFuncSetAttribute(corr_volume_kernel,
                         cudaFuncAttributeMaxDynamicSharedMemorySize, SMEM_BYTES);
    corr_volume_kernel<<<4 * (HH / YP) * 2 * 2, NTHREADS, SMEM_BYTES>>>(t1, t2, out);
}